// round 1
// baseline (speedup 1.0000x reference)
#include <cuda_runtime.h>
#include <mma.h>
#include <math.h>

using namespace nvcuda;

#define BB  128
#define SS  256
#define II  512
#define HH  1024
#define OO  512
#define TT  128
#define G4H 4096

// ---------------- static device scratch (no allocs allowed) ----------------
__device__ float g_P[(size_t)BB * SS * G4H];   // encoder input preactivations (512 MB)
__device__ float g_h0[BB * HH];
__device__ float g_h1[BB * HH];
__device__ float g_c[BB * HH];
__device__ float g_Weff[G4H * HH];             // W_hh_dec + W_ih_dec @ W_proj
__device__ float g_WprojT[HH * OO];            // W_proj transposed
__device__ float g_benc[G4H];
__device__ float g_bdec[G4H];
__device__ float g_beff[G4H];
__device__ float g_Hall[(size_t)BB * TT * HH]; // decoder hidden states (64 MB)

// ---------------- shared memory layout ----------------
struct SmemAB { float a[64][40]; float b[64][40]; };  // 40: float4-aligned + wmma ldm%4==0
union Smem { SmemAB ab; float c[64][68]; };

// ---------------- small helper kernels ----------------
__global__ void k_zero(float* p, int n) {
    int i = blockIdx.x * blockDim.x + threadIdx.x;
    if (i < n) p[i] = 0.f;
}

__global__ void k_vec_add(const float* __restrict__ a, const float* __restrict__ b,
                          float* __restrict__ o, int n) {
    int i = blockIdx.x * blockDim.x + threadIdx.x;
    if (i < n) o[i] = a[i] + b[i];
}

// dst[k][o] = src[o][k]   (src: [OO][HH], dst: [HH][OO])
__global__ void k_transpose_po(const float* __restrict__ src, float* __restrict__ dst) {
    int i = blockIdx.x * blockDim.x + threadIdx.x;
    if (i < HH * OO) {
        int k = i / OO, o = i % OO;
        dst[i] = src[(size_t)o * HH + k];
    }
}

// beff[n] = bdec[n] + sum_o Wih_dec[n][o] * bproj[o]
__global__ void k_beff(const float* __restrict__ Wih, const float* __restrict__ bproj,
                       const float* __restrict__ bdec, float* __restrict__ beff) {
    int n = blockIdx.x * blockDim.x + threadIdx.x;
    if (n < G4H) {
        float s = bdec[n];
        const float* wr = Wih + (size_t)n * OO;
        #pragma unroll 8
        for (int o = 0; o < OO; o++) s += wr[o] * bproj[o];
        beff[n] = s;
    }
}

// ---------------- generic 64x64-tile tf32 GEMM: C = A * B^T (+bias[n]) (+addm) ----------------
// A: [M][lda] row-major, Bm: [N][ldb] row-major (so C[m][n] = sum_k A[m][k]*Bm[n][k])
// grid: (N/64, M/64), block: 256 (8 warps, warp tile 16x32)
__global__ void k_gemm64(const float* __restrict__ A, int lda,
                         const float* __restrict__ Bm, int ldb,
                         float* __restrict__ C, int ldc, int K,
                         const float* __restrict__ bias,
                         const float* __restrict__ addm) {
    __shared__ Smem sm;
    const int tid = threadIdx.x;
    const int m0 = blockIdx.y * 64;
    const int n0 = blockIdx.x * 64;
    const int w  = tid >> 5;
    const int wm = w >> 1, wn = w & 1;

    wmma::fragment<wmma::accumulator, 16, 16, 8, float> c0, c1;
    wmma::fill_fragment(c0, 0.f);
    wmma::fill_fragment(c1, 0.f);

    for (int k0 = 0; k0 < K; k0 += 32) {
        #pragma unroll
        for (int r = 0; r < 2; r++) {
            int i = tid + 256 * r;              // 0..511 float4 slots
            int row = i >> 3, q = i & 7;
            *(float4*)&sm.ab.a[row][q * 4] =
                *(const float4*)&A[(size_t)(m0 + row) * lda + k0 + q * 4];
            *(float4*)&sm.ab.b[row][q * 4] =
                *(const float4*)&Bm[(size_t)(n0 + row) * ldb + k0 + q * 4];
        }
        __syncthreads();
        #pragma unroll
        for (int kk = 0; kk < 4; kk++) {
            wmma::fragment<wmma::matrix_a, 16, 16, 8, wmma::precision::tf32, wmma::row_major> af;
            wmma::fragment<wmma::matrix_b, 16, 16, 8, wmma::precision::tf32, wmma::col_major> bf0, bf1;
            wmma::load_matrix_sync(af,  &sm.ab.a[wm * 16][kk * 8], 40);
            wmma::load_matrix_sync(bf0, &sm.ab.b[wn * 32][kk * 8], 40);
            wmma::load_matrix_sync(bf1, &sm.ab.b[wn * 32 + 16][kk * 8], 40);
            #pragma unroll
            for (int i = 0; i < af.num_elements; i++)  af.x[i]  = wmma::__float_to_tf32(af.x[i]);
            #pragma unroll
            for (int i = 0; i < bf0.num_elements; i++) bf0.x[i] = wmma::__float_to_tf32(bf0.x[i]);
            #pragma unroll
            for (int i = 0; i < bf1.num_elements; i++) bf1.x[i] = wmma::__float_to_tf32(bf1.x[i]);
            wmma::mma_sync(c0, af, bf0, c0);
            wmma::mma_sync(c1, af, bf1, c1);
        }
        __syncthreads();
    }

    wmma::store_matrix_sync(&sm.c[wm * 16][wn * 32],      c0, 68, wmma::mem_row_major);
    wmma::store_matrix_sync(&sm.c[wm * 16][wn * 32 + 16], c1, 68, wmma::mem_row_major);
    __syncthreads();

    for (int idx = tid; idx < 64 * 64; idx += 256) {
        int m = idx >> 6, n = idx & 63;
        float v = sm.c[m][n];
        if (bias) v += bias[n0 + n];
        if (addm) v += addm[(size_t)(m0 + m) * ldc + n0 + n];
        C[(size_t)(m0 + m) * ldc + n0 + n] = v;
    }
}

// ---------------- fused LSTM step: gates GEMM (all 4 gates) + pointwise ----------------
// gates[b][g*H+n] = sum_k hin[b][k]*W[g*H+n][k] + add[b*addstride + g*H + n]
// CTA: 64 batch rows x 16 gate-columns (x4 gates). grid (HH/16, BB/64)=(64,2)
__global__ void k_lstm_step(const float* __restrict__ hin,
                            float* __restrict__ hout,
                            float* __restrict__ cst,
                            const float* __restrict__ W,     // [4H][H]
                            const float* __restrict__ add, int addstride,
                            float* __restrict__ hall, int hallstride) {
    __shared__ Smem sm;
    const int tid = threadIdx.x;
    const int m0 = blockIdx.y * 64;
    const int nb = blockIdx.x * 16;
    const int w  = tid >> 5;
    const int wm = w >> 1, wn = w & 1;

    wmma::fragment<wmma::accumulator, 16, 16, 8, float> c0, c1;
    wmma::fill_fragment(c0, 0.f);
    wmma::fill_fragment(c1, 0.f);

    for (int k0 = 0; k0 < HH; k0 += 32) {
        #pragma unroll
        for (int r = 0; r < 2; r++) {
            int i = tid + 256 * r;
            int row = i >> 3, q = i & 7;
            *(float4*)&sm.ab.a[row][q * 4] =
                *(const float4*)&hin[(size_t)(m0 + row) * HH + k0 + q * 4];
            int wr = (row >> 4) * HH + nb + (row & 15);   // gate-major column mapping
            *(float4*)&sm.ab.b[row][q * 4] =
                *(const float4*)&W[(size_t)wr * HH + k0 + q * 4];
        }
        __syncthreads();
        #pragma unroll
        for (int kk = 0; kk < 4; kk++) {
            wmma::fragment<wmma::matrix_a, 16, 16, 8, wmma::precision::tf32, wmma::row_major> af;
            wmma::fragment<wmma::matrix_b, 16, 16, 8, wmma::precision::tf32, wmma::col_major> bf0, bf1;
            wmma::load_matrix_sync(af,  &sm.ab.a[wm * 16][kk * 8], 40);
            wmma::load_matrix_sync(bf0, &sm.ab.b[wn * 32][kk * 8], 40);
            wmma::load_matrix_sync(bf1, &sm.ab.b[wn * 32 + 16][kk * 8], 40);
            #pragma unroll
            for (int i = 0; i < af.num_elements; i++)  af.x[i]  = wmma::__float_to_tf32(af.x[i]);
            #pragma unroll
            for (int i = 0; i < bf0.num_elements; i++) bf0.x[i] = wmma::__float_to_tf32(bf0.x[i]);
            #pragma unroll
            for (int i = 0; i < bf1.num_elements; i++) bf1.x[i] = wmma::__float_to_tf32(bf1.x[i]);
            wmma::mma_sync(c0, af, bf0, c0);
            wmma::mma_sync(c1, af, bf1, c1);
        }
        __syncthreads();
    }

    wmma::store_matrix_sync(&sm.c[wm * 16][wn * 32],      c0, 68, wmma::mem_row_major);
    wmma::store_matrix_sync(&sm.c[wm * 16][wn * 32 + 16], c1, 68, wmma::mem_row_major);
    __syncthreads();

    // pointwise LSTM update: columns [0:16)=i, [16:32)=f, [32:48)=g, [48:64)=o
    for (int idx = tid; idx < 64 * 16; idx += 256) {
        int m = idx >> 4, j = idx & 15;
        int b = m0 + m;
        int n = nb + j;
        size_t ab = (size_t)b * addstride;
        float gi = sm.c[m][j]      + add[ab + 0 * HH + n];
        float gf = sm.c[m][16 + j] + add[ab + 1 * HH + n];
        float gg = sm.c[m][32 + j] + add[ab + 2 * HH + n];
        float go = sm.c[m][48 + j] + add[ab + 3 * HH + n];
        float co = cst[(size_t)b * HH + n];
        float si = 1.f / (1.f + expf(-gi));
        float sf = 1.f / (1.f + expf(-gf));
        float so = 1.f / (1.f + expf(-go));
        float cn = sf * co + si * tanhf(gg);
        float hn = so * tanhf(cn);
        cst[(size_t)b * HH + n]  = cn;
        hout[(size_t)b * HH + n] = hn;
        if (hall) hall[(size_t)b * hallstride + n] = hn;
    }
}

// ---------------- host launch ----------------
extern "C" void kernel_launch(void* const* d_in, const int* in_sizes, int n_in,
                              void* d_out, int out_size) {
    // tgt_len may or may not be materialized as input[1] (scalar). Detect by size.
    int wbase = (n_in >= 12 && in_sizes[1] == 1) ? 2 : 1;

    const float* x      = (const float*)d_in[0];
    const float* Wih_e  = (const float*)d_in[wbase + 0];
    const float* Whh_e  = (const float*)d_in[wbase + 1];
    const float* bih_e  = (const float*)d_in[wbase + 2];
    const float* bhh_e  = (const float*)d_in[wbase + 3];
    const float* Wih_d  = (const float*)d_in[wbase + 4];
    const float* Whh_d  = (const float*)d_in[wbase + 5];
    const float* bih_d  = (const float*)d_in[wbase + 6];
    const float* bhh_d  = (const float*)d_in[wbase + 7];
    const float* Wproj  = (const float*)d_in[wbase + 8];
    const float* bproj  = (const float*)d_in[wbase + 9];
    float* out = (float*)d_out;

    float *P, *h0, *h1, *c, *Weff, *WpT, *benc, *bdec, *beff, *Hall;
    cudaGetSymbolAddress((void**)&P,    g_P);
    cudaGetSymbolAddress((void**)&h0,   g_h0);
    cudaGetSymbolAddress((void**)&h1,   g_h1);
    cudaGetSymbolAddress((void**)&c,    g_c);
    cudaGetSymbolAddress((void**)&Weff, g_Weff);
    cudaGetSymbolAddress((void**)&WpT,  g_WprojT);
    cudaGetSymbolAddress((void**)&benc, g_benc);
    cudaGetSymbolAddress((void**)&bdec, g_bdec);
    cudaGetSymbolAddress((void**)&beff, g_beff);
    cudaGetSymbolAddress((void**)&Hall, g_Hall);

    // init state
    k_zero<<<(BB * HH + 255) / 256, 256>>>(h0, BB * HH);
    k_zero<<<(BB * HH + 255) / 256, 256>>>(c,  BB * HH);

    // combined biases
    k_vec_add<<<16, 256>>>(bih_e, bhh_e, benc, G4H);
    k_vec_add<<<16, 256>>>(bih_d, bhh_d, bdec, G4H);

    // W_proj^T  (for W_eff GEMM)
    k_transpose_po<<<(HH * OO + 255) / 256, 256>>>(Wproj, WpT);

    // W_eff = W_ih_dec @ W_proj + W_hh_dec   : [4096,1024]
    k_gemm64<<<dim3(HH / 64, G4H / 64), 256>>>(Wih_d, OO, WpT, OO, Weff, HH, OO,
                                               nullptr, Whh_d);
    // b_eff = b_dec + W_ih_dec @ b_proj
    k_beff<<<16, 256>>>(Wih_d, bproj, bdec, beff);

    // P = X @ W_ih_enc^T + b_enc  : [B*S, 4H]
    k_gemm64<<<dim3(G4H / 64, (BB * SS) / 64), 256>>>(x, II, Wih_e, II, P, G4H, II,
                                                      benc, nullptr);

    float* hbuf[2] = { h0, h1 };

    // encoder recurrence: gates = h @ W_hh_enc^T + P[:, s, :]
    for (int s = 0; s < SS; s++) {
        k_lstm_step<<<dim3(HH / 16, BB / 64), 256>>>(
            hbuf[s & 1], hbuf[(s + 1) & 1], c, Whh_e,
            P + (size_t)s * G4H, SS * G4H, nullptr, 0);
    }

    // decoder recurrence (folded feedback):
    //   t==0: gates = h_enc @ W_hh_dec^T + b_dec           (inp = 0)
    //   t>=1: gates = h @ (W_hh_dec + W_ih_dec W_proj)^T + b_eff
    for (int t = 0; t < TT; t++) {
        int g = SS + t;
        k_lstm_step<<<dim3(HH / 16, BB / 64), 256>>>(
            hbuf[g & 1], hbuf[(g + 1) & 1], c,
            (t == 0) ? Whh_d : Weff,
            (t == 0) ? bdec : beff, 0,
            Hall + (size_t)t * HH, TT * HH);
    }

    // Y = H_all @ W_proj^T + b_proj  -> out [B, T, O]
    k_gemm64<<<dim3(OO / 64, (BB * TT) / 64), 256>>>(Hall, HH, Wproj, HH, out, OO, HH,
                                                     bproj, nullptr);
}

// round 2
// speedup vs baseline: 1.2681x; 1.2681x over previous
#include <cuda_runtime.h>
#include <mma.h>
#include <math.h>

using namespace nvcuda;

#define BB  128
#define SS  256
#define II  512
#define HH  1024
#define OO  512
#define TT  128
#define G4H 4096
#define NSTEP (SS + TT)
#define NCTA_REC 128

// ---------------- static device scratch (no allocs allowed) ----------------
__device__ float g_P[(size_t)BB * SS * G4H];   // encoder input preactivations
__device__ float g_h0[BB * HH];
__device__ float g_h1[BB * HH];
__device__ float g_Weff[G4H * HH];             // W_hh_dec + W_ih_dec @ W_proj
__device__ float g_WpT[HH * OO];               // W_proj transposed
__device__ float g_benc[G4H];
__device__ float g_bdec[G4H];
__device__ float g_beff[G4H];
__device__ float g_Hall[(size_t)BB * TT * HH]; // decoder hidden states
__device__ unsigned g_bar;                     // grid barrier counter

// ---------------- cp.async helpers ----------------
__device__ __forceinline__ void cp_cg16(void* s, const void* g) {
    unsigned sa = (unsigned)__cvta_generic_to_shared(s);
    asm volatile("cp.async.cg.shared.global [%0], [%1], 16;" :: "r"(sa), "l"(g));
}
__device__ __forceinline__ void cp_ca16(void* s, const void* g) {
    unsigned sa = (unsigned)__cvta_generic_to_shared(s);
    asm volatile("cp.async.ca.shared.global [%0], [%1], 16;" :: "r"(sa), "l"(g));
}
__device__ __forceinline__ void cp_commit() { asm volatile("cp.async.commit_group;"); }
template <int N>
__device__ __forceinline__ void cp_wait() { asm volatile("cp.async.wait_group %0;" :: "n"(N)); }

// ---------------- grid barrier (all NCTA_REC CTAs co-resident) ----------------
__device__ __forceinline__ void gridbar(int& epoch) {
    epoch++;
    __threadfence();          // make this thread's global writes visible device-wide
    __syncthreads();          // all threads of CTA fenced before signaling
    if (threadIdx.x == 0) {
        atomicAdd(&g_bar, 1u);
        const unsigned tgt = (unsigned)NCTA_REC * (unsigned)epoch;
        volatile unsigned* p = &g_bar;
        while (*p < tgt) { }
    }
    __syncthreads();
}

__global__ void k_reset_bar() { g_bar = 0u; }

// ---------------- small helper kernels ----------------
__global__ void k_vec_add(const float* __restrict__ a, const float* __restrict__ b,
                          float* __restrict__ o, int n) {
    int i = blockIdx.x * blockDim.x + threadIdx.x;
    if (i < n) o[i] = a[i] + b[i];
}

// dst[k][o] = src[o][k]   (src: [OO][HH], dst: [HH][OO])
__global__ void k_transpose_po(const float* __restrict__ src, float* __restrict__ dst) {
    int i = blockIdx.x * blockDim.x + threadIdx.x;
    if (i < HH * OO) {
        int k = i / OO, o = i % OO;
        dst[i] = src[(size_t)o * HH + k];
    }
}

// beff[n] = bdec[n] + sum_o Wih_dec[n][o] * bproj[o]
__global__ void k_beff(const float* __restrict__ Wih, const float* __restrict__ bproj,
                       const float* __restrict__ bdec, float* __restrict__ beff) {
    int n = blockIdx.x * blockDim.x + threadIdx.x;
    if (n < G4H) {
        float s = bdec[n];
        const float* wr = Wih + (size_t)n * OO;
        #pragma unroll 8
        for (int o = 0; o < OO; o++) s += wr[o] * bproj[o];
        beff[n] = s;
    }
}

// ---------------- pipelined 128x64-tile tf32 GEMM: C = A * B^T (+bias[n]) (+addm) ----
// A: [M][lda] row-major, Bm: [N][ldb] row-major.  M%128==0, N%64==0, K%16==0.
// grid: (N/64, M/128), block 256 (8 warps, warp tile 32x32)
struct __align__(16) G128Pipe { float a[2][128][20]; float b[2][64][20]; };
union  __align__(16) G128Smem { G128Pipe p; float c[128][68]; };

__global__ void __launch_bounds__(256) k_gemm128(
        const float* __restrict__ A, int lda,
        const float* __restrict__ Bm, int ldb,
        float* __restrict__ C, int ldc, int K,
        const float* __restrict__ bias,
        const float* __restrict__ addm) {
    __shared__ G128Smem sm;
    const int tid = threadIdx.x;
    const int m0 = blockIdx.y * 128;
    const int n0 = blockIdx.x * 64;
    const int w = tid >> 5, wm = w >> 1, wn = w & 1;
    const int nIt = K >> 4;

    auto load = [&](int st, int k0) {
        #pragma unroll
        for (int r = 0; r < 2; r++) {                       // A: 512 quads
            int t = tid + 256 * r;
            int row = t >> 2, q = t & 3;
            cp_cg16(&sm.p.a[st][row][q * 4], &A[(size_t)(m0 + row) * lda + k0 + q * 4]);
        }
        {                                                   // B: 256 quads
            int row = tid >> 2, q = tid & 3;
            cp_ca16(&sm.p.b[st][row][q * 4], &Bm[(size_t)(n0 + row) * ldb + k0 + q * 4]);
        }
    };

    wmma::fragment<wmma::accumulator, 16, 16, 8, float> cc[2][2];
    #pragma unroll
    for (int i = 0; i < 2; i++)
        #pragma unroll
        for (int j = 0; j < 2; j++) wmma::fill_fragment(cc[i][j], 0.f);

    load(0, 0); cp_commit();
    for (int it = 0; it < nIt; it++) {
        if (it + 1 < nIt) { load((it + 1) & 1, (it + 1) << 4); cp_commit(); cp_wait<1>(); }
        else              { cp_wait<0>(); }
        __syncthreads();
        int st = it & 1;
        #pragma unroll
        for (int kk = 0; kk < 2; kk++) {
            wmma::fragment<wmma::matrix_a, 16, 16, 8, wmma::precision::tf32, wmma::row_major> a0, a1;
            wmma::fragment<wmma::matrix_b, 16, 16, 8, wmma::precision::tf32, wmma::col_major> b0, b1;
            wmma::load_matrix_sync(a0, &sm.p.a[st][wm * 32][kk * 8], 20);
            wmma::load_matrix_sync(a1, &sm.p.a[st][wm * 32 + 16][kk * 8], 20);
            wmma::load_matrix_sync(b0, &sm.p.b[st][wn * 32][kk * 8], 20);
            wmma::load_matrix_sync(b1, &sm.p.b[st][wn * 32 + 16][kk * 8], 20);
            #pragma unroll
            for (int i = 0; i < a0.num_elements; i++) { a0.x[i] = wmma::__float_to_tf32(a0.x[i]); a1.x[i] = wmma::__float_to_tf32(a1.x[i]); }
            #pragma unroll
            for (int i = 0; i < b0.num_elements; i++) { b0.x[i] = wmma::__float_to_tf32(b0.x[i]); b1.x[i] = wmma::__float_to_tf32(b1.x[i]); }
            wmma::mma_sync(cc[0][0], a0, b0, cc[0][0]);
            wmma::mma_sync(cc[0][1], a0, b1, cc[0][1]);
            wmma::mma_sync(cc[1][0], a1, b0, cc[1][0]);
            wmma::mma_sync(cc[1][1], a1, b1, cc[1][1]);
        }
        __syncthreads();
    }

    #pragma unroll
    for (int i = 0; i < 2; i++)
        #pragma unroll
        for (int j = 0; j < 2; j++)
            wmma::store_matrix_sync(&sm.c[wm * 32 + i * 16][wn * 32 + j * 16], cc[i][j], 68,
                                    wmma::mem_row_major);
    __syncthreads();

    for (int idx = tid; idx < 128 * 64; idx += 256) {
        int m = idx >> 6, n = idx & 63;
        float v = sm.c[m][n];
        if (bias) v += bias[n0 + n];
        if (addm) v += addm[(size_t)(m0 + m) * ldc + n0 + n];
        C[(size_t)(m0 + m) * ldc + n0 + n] = v;
    }
}

// ---------------- persistent fused recurrence kernel ----------------
// 128 CTAs: cta = mt + 2*nt; tile = 64 batch rows x 16 gate-cols (x4 gates).
// Runs all SS+TT steps with a grid barrier between steps. c-state lives in SMEM.
struct __align__(16) RecPipe { float a[2][64][40]; float b[2][64][40]; };
union  __align__(16) RecSmem { RecPipe p; float c[64][68]; };

__global__ void __launch_bounds__(256, 1) k_recurrence(
        const float* __restrict__ P,
        const float* __restrict__ WhhE,
        const float* __restrict__ WhhD,
        const float* __restrict__ Weff,
        const float* __restrict__ bdec,
        const float* __restrict__ beff,
        float* __restrict__ h0,
        float* __restrict__ h1,
        float* __restrict__ Hall) {
    __shared__ RecSmem sm;
    __shared__ float cst[64][16];
    const int tid = threadIdx.x;
    const int cta = blockIdx.x;
    const int mt = cta & 1, nt = cta >> 1;
    const int m0 = mt * 64, nb = nt * 16;
    const int w = tid >> 5, wm = w >> 1, wn = w & 1;

    // init: c-state (SMEM) and this CTA's slice of h0 to zero
    for (int i = tid; i < 64 * 16; i += 256) {
        int m = i >> 4, j = i & 15;
        cst[m][j] = 0.f;
        h0[(size_t)(m0 + m) * HH + nb + j] = 0.f;
    }
    int epoch = 0;
    gridbar(epoch);   // h0 fully zeroed across all CTAs

    for (int s = 0; s < NSTEP; s++) {
        const float* hin  = (s & 1) ? h1 : h0;
        float*       hout = (s & 1) ? h0 : h1;
        const float* W;
        const float* add;
        int adds;
        if (s < SS)       { W = WhhE; add = P + (size_t)s * G4H; adds = SS * G4H; }
        else if (s == SS) { W = WhhD; add = bdec; adds = 0; }
        else              { W = Weff; add = beff; adds = 0; }

        auto load = [&](int st, int k0) {
            #pragma unroll
            for (int r = 0; r < 2; r++) {
                int t = tid + 256 * r;           // 0..511
                int row = t >> 3, q = t & 7;     // 64 rows x 8 quads (32 floats)
                cp_cg16(&sm.p.a[st][row][q * 4],
                        &hin[(size_t)(m0 + row) * HH + k0 + q * 4]);
                int wr = (row >> 4) * HH + nb + (row & 15);   // gate-major mapping
                cp_ca16(&sm.p.b[st][row][q * 4],
                        &W[(size_t)wr * HH + k0 + q * 4]);
            }
        };

        wmma::fragment<wmma::accumulator, 16, 16, 8, float> c0, c1;
        wmma::fill_fragment(c0, 0.f);
        wmma::fill_fragment(c1, 0.f);

        load(0, 0); cp_commit();
        for (int it = 0; it < 32; it++) {
            if (it + 1 < 32) { load((it + 1) & 1, (it + 1) * 32); cp_commit(); cp_wait<1>(); }
            else             { cp_wait<0>(); }
            __syncthreads();
            int st = it & 1;
            #pragma unroll
            for (int kk = 0; kk < 4; kk++) {
                wmma::fragment<wmma::matrix_a, 16, 16, 8, wmma::precision::tf32, wmma::row_major> af;
                wmma::fragment<wmma::matrix_b, 16, 16, 8, wmma::precision::tf32, wmma::col_major> b0, b1;
                wmma::load_matrix_sync(af, &sm.p.a[st][wm * 16][kk * 8], 40);
                wmma::load_matrix_sync(b0, &sm.p.b[st][wn * 32][kk * 8], 40);
                wmma::load_matrix_sync(b1, &sm.p.b[st][wn * 32 + 16][kk * 8], 40);
                #pragma unroll
                for (int i = 0; i < af.num_elements; i++) af.x[i] = wmma::__float_to_tf32(af.x[i]);
                #pragma unroll
                for (int i = 0; i < b0.num_elements; i++) { b0.x[i] = wmma::__float_to_tf32(b0.x[i]); b1.x[i] = wmma::__float_to_tf32(b1.x[i]); }
                wmma::mma_sync(c0, af, b0, c0);
                wmma::mma_sync(c1, af, b1, c1);
            }
            __syncthreads();
        }

        wmma::store_matrix_sync(&sm.c[wm * 16][wn * 32],      c0, 68, wmma::mem_row_major);
        wmma::store_matrix_sync(&sm.c[wm * 16][wn * 32 + 16], c1, 68, wmma::mem_row_major);
        __syncthreads();

        // pointwise LSTM update: cols [0:16)=i, [16:32)=f, [32:48)=g, [48:64)=o
        for (int idx = tid; idx < 64 * 16; idx += 256) {
            int m = idx >> 4, j = idx & 15;
            int b = m0 + m, n = nb + j;
            size_t ab = (size_t)b * adds;
            float gi = sm.c[m][j]      + add[ab + 0 * HH + n];
            float gf = sm.c[m][16 + j] + add[ab + 1 * HH + n];
            float gg = sm.c[m][32 + j] + add[ab + 2 * HH + n];
            float go = sm.c[m][48 + j] + add[ab + 3 * HH + n];
            float co = cst[m][j];
            float si = 1.f / (1.f + expf(-gi));
            float sf = 1.f / (1.f + expf(-gf));
            float so = 1.f / (1.f + expf(-go));
            float cn = sf * co + si * tanhf(gg);
            float hn = so * tanhf(cn);
            cst[m][j] = cn;
            hout[(size_t)b * HH + n] = hn;
            if (s >= SS) Hall[(size_t)b * (TT * HH) + (size_t)(s - SS) * HH + n] = hn;
        }

        if (s < NSTEP - 1) gridbar(epoch);
    }
}

// ---------------- host launch ----------------
extern "C" void kernel_launch(void* const* d_in, const int* in_sizes, int n_in,
                              void* d_out, int out_size) {
    int wbase = (n_in >= 12 && in_sizes[1] == 1) ? 2 : 1;

    const float* x     = (const float*)d_in[0];
    const float* Wih_e = (const float*)d_in[wbase + 0];
    const float* Whh_e = (const float*)d_in[wbase + 1];
    const float* bih_e = (const float*)d_in[wbase + 2];
    const float* bhh_e = (const float*)d_in[wbase + 3];
    const float* Wih_d = (const float*)d_in[wbase + 4];
    const float* Whh_d = (const float*)d_in[wbase + 5];
    const float* bih_d = (const float*)d_in[wbase + 6];
    const float* bhh_d = (const float*)d_in[wbase + 7];
    const float* Wproj = (const float*)d_in[wbase + 8];
    const float* bproj = (const float*)d_in[wbase + 9];
    float* out = (float*)d_out;

    float *P, *h0, *h1, *Weff, *WpT, *benc, *bdec, *beff, *Hall;
    cudaGetSymbolAddress((void**)&P,    g_P);
    cudaGetSymbolAddress((void**)&h0,   g_h0);
    cudaGetSymbolAddress((void**)&h1,   g_h1);
    cudaGetSymbolAddress((void**)&Weff, g_Weff);
    cudaGetSymbolAddress((void**)&WpT,  g_WpT);
    cudaGetSymbolAddress((void**)&benc, g_benc);
    cudaGetSymbolAddress((void**)&bdec, g_bdec);
    cudaGetSymbolAddress((void**)&beff, g_beff);
    cudaGetSymbolAddress((void**)&Hall, g_Hall);

    // combined biases
    k_vec_add<<<16, 256>>>(bih_e, bhh_e, benc, G4H);
    k_vec_add<<<16, 256>>>(bih_d, bhh_d, bdec, G4H);

    // W_proj^T
    k_transpose_po<<<(HH * OO + 255) / 256, 256>>>(Wproj, WpT);

    // W_eff = W_ih_dec @ W_proj + W_hh_dec : [4096,1024], K=512
    k_gemm128<<<dim3(HH / 64, G4H / 128), 256>>>(Wih_d, OO, WpT, OO, Weff, HH, OO,
                                                 nullptr, Whh_d);
    // b_eff = b_dec + W_ih_dec @ b_proj
    k_beff<<<16, 256>>>(Wih_d, bproj, bdec, beff);

    // P = X @ W_ih_enc^T + b_enc : [B*S, 4H], K=512
    k_gemm128<<<dim3(G4H / 64, (BB * SS) / 128), 256>>>(x, II, Wih_e, II, P, G4H, II,
                                                        benc, nullptr);

    // persistent fused recurrence (encoder + decoder), 384 steps in one launch
    k_reset_bar<<<1, 1>>>();
    k_recurrence<<<NCTA_REC, 256>>>(P, Whh_e, Whh_d, Weff, bdec, beff, h0, h1, Hall);

    // Y = H_all @ W_proj^T + b_proj -> out [B, T, O], K=1024
    k_gemm128<<<dim3(OO / 64, (BB * TT) / 128), 256>>>(Hall, HH, Wproj, HH, out, OO, HH,
                                                       bproj, nullptr);
}